// round 2
// baseline (speedup 1.0000x reference)
#include <cuda_runtime.h>

#define BB 4
#define LL 4096
#define DD 1024

// Scratch (device globals; no allocation allowed in kernel_launch)
__device__ float g_H[(size_t)BB * LL * DD];   // scan outputs h_t (only first Nb rows/batch used)
__device__ float g_ps[BB * LL];               // compacted clipped boundary probs
__device__ int   g_cidx[BB * LL];             // plug_back_idx = cumsum(mask)-1
__device__ int   g_nb[BB];                    // number of boundaries per batch
__device__ int   g_mtype;                     // 0 = uint8, 1 = int32, 2 = float32

// ---------------------------------------------------------------------------
// Kernel 0: detect the storage type of boundary_mask.
// token 0 is always True:
//   float32 -> bytes [00 00 80 3F]          (check bytes 2,3)
//   int32   -> bytes [01 00 00 00], zeros at pos%4!=0 throughout
//   uint8   -> ~25% ones at ALL byte positions
// Reading the first 16KB is in-bounds for every candidate (uint8 buffer is
// exactly 16KB; wider types are larger).
// ---------------------------------------------------------------------------
__global__ void detect_kernel(const unsigned char* __restrict__ mask) {
    __shared__ int misaligned_nonzero[1];
    if (threadIdx.x == 0) misaligned_nonzero[0] = 0;
    __syncthreads();
    int found = 0;
    for (int i = threadIdx.x; i < LL * BB; i += blockDim.x) {  // 16384 bytes
        if ((i & 3) != 0 && mask[i] != 0) found = 1;
    }
    if (found) atomicOr(misaligned_nonzero, 1);
    __syncthreads();
    if (threadIdx.x == 0) {
        if (mask[2] == 0x80 && mask[3] == 0x3F) g_mtype = 2;      // float32
        else if (misaligned_nonzero[0])         g_mtype = 0;      // uint8
        else                                    g_mtype = 1;      // int32
    }
}

__device__ __forceinline__ int read_mask(const unsigned char* mask, int idx, int mtype) {
    if (mtype == 1) return ((const int*)mask)[idx] != 0;
    if (mtype == 2) return ((const float*)mask)[idx] != 0.0f;
    return mask[idx] != 0;
}

// ---------------------------------------------------------------------------
// Kernel A: per-batch prefix sum over mask -> c(l), compacted p list, Nb.
// One block of 1024 threads per batch; each thread handles 4 of L=4096 tokens.
// ---------------------------------------------------------------------------
__global__ void prep_kernel(const float* __restrict__ prob,
                            const unsigned char* __restrict__ mask) {
    int b   = blockIdx.x;
    int tid = threadIdx.x;           // 0..1023
    int base = tid * 4;
    int mtype = g_mtype;

    int m[4];
#pragma unroll
    for (int i = 0; i < 4; i++) m[i] = read_mask(mask, b * LL + base + i, mtype);
    int tsum = m[0] + m[1] + m[2] + m[3];

    int lane = tid & 31, wid = tid >> 5;
    int v = tsum;  // warp inclusive scan of per-thread sums
#pragma unroll
    for (int o = 1; o < 32; o <<= 1) {
        int n = __shfl_up_sync(0xffffffffu, v, o);
        if (lane >= o) v += n;
    }
    __shared__ int wsum[32];
    if (lane == 31) wsum[wid] = v;
    __syncthreads();
    if (wid == 0) {
        int wv = wsum[lane];
#pragma unroll
        for (int o = 1; o < 32; o <<= 1) {
            int n = __shfl_up_sync(0xffffffffu, wv, o);
            if (lane >= o) wv += n;
        }
        wsum[lane] = wv;
    }
    __syncthreads();
    int warpExcl   = (wid == 0) ? 0 : wsum[wid - 1];
    int threadExcl = warpExcl + (v - tsum);

    int run = threadExcl;
#pragma unroll
    for (int i = 0; i < 4; i++) {
        run += m[i];
        g_cidx[(size_t)b * LL + base + i] = run - 1;
        if (m[i]) {
            float p = prob[((size_t)b * LL + base + i) * 2 + 1];
            p = fminf(fmaxf(p, 1e-4f), 1.0f - 1e-4f);
            g_ps[(size_t)b * LL + (run - 1)] = p;
        }
    }
    if (tid == 1023) g_nb[b] = run;   // total boundary count
}

// ---------------------------------------------------------------------------
// Kernel B: linear recurrence h_t = (1-p_t)*h_{t-1} + p_t*x[t] per channel.
// Grid (D/256, B); thread d scans t = 0..Nb-1. Loads coalesced across d.
// Off-chain a=1-p, u=p*x keep the dependency chain to one FMA (4 cyc/step).
// ---------------------------------------------------------------------------
__global__ void scan_kernel(const float* __restrict__ hidden) {
    int b = blockIdx.y;
    int d = blockIdx.x * blockDim.x + threadIdx.x;
    int nb = g_nb[b];

    const float* x  = hidden + (size_t)b * LL * DD + d;
    float*       Hp = g_H    + (size_t)b * LL * DD + d;
    const float* ps = g_ps   + (size_t)b * LL;

    float h = 0.f;
    int t = 0;
    for (; t + 4 <= nb; t += 4) {
        float p0 = ps[t + 0], p1 = ps[t + 1], p2 = ps[t + 2], p3 = ps[t + 3];
        float x0 = x[(size_t)(t + 0) * DD];
        float x1 = x[(size_t)(t + 1) * DD];
        float x2 = x[(size_t)(t + 2) * DD];
        float x3 = x[(size_t)(t + 3) * DD];
        float u0 = p0 * x0, u1 = p1 * x1, u2 = p2 * x2, u3 = p3 * x3;
        h = fmaf(1.f - p0, h, u0); Hp[(size_t)(t + 0) * DD] = h;
        h = fmaf(1.f - p1, h, u1); Hp[(size_t)(t + 1) * DD] = h;
        h = fmaf(1.f - p2, h, u2); Hp[(size_t)(t + 2) * DD] = h;
        h = fmaf(1.f - p3, h, u3); Hp[(size_t)(t + 3) * DD] = h;
    }
    for (; t < nb; t++) {
        float p = ps[t];
        h = fmaf(1.f - p, h, p * x[(size_t)t * DD]);
        Hp[(size_t)t * DD] = h;
    }
}

// ---------------------------------------------------------------------------
// Kernel C: out[b,l,:] = H[b, c(l), :], vectorized float4.
// One block of 256 threads per output row (256 float4 = 1024 floats).
// c(l) is a uniform broadcast load per row; H rows are hot in L2.
// ---------------------------------------------------------------------------
__global__ void scatter_kernel(float* __restrict__ out) {
    int idx = blockIdx.x * blockDim.x + threadIdx.x;  // over B*L*256
    int row = idx >> 8;     // b*L + l
    int d4  = idx & 255;
    int b   = row >> 12;    // L = 4096
    int c   = g_cidx[row];

    const float4* Hv = (const float4*)g_H;
    float4 val = Hv[(((size_t)b << 12) + (size_t)c) * 256 + d4];
    ((float4*)out)[idx] = val;
}

extern "C" void kernel_launch(void* const* d_in, const int* in_sizes, int n_in,
                              void* d_out, int out_size) {
    const float*         hidden = (const float*)d_in[0];
    const float*         prob   = (const float*)d_in[1];
    const unsigned char* mask   = (const unsigned char*)d_in[2];
    float*               out    = (float*)d_out;

    detect_kernel<<<1, 512>>>(mask);
    prep_kernel<<<BB, 1024>>>(prob, mask);
    scan_kernel<<<dim3(DD / 256, BB), 256>>>(hidden);
    scatter_kernel<<<BB * LL, 256>>>(out);
}

// round 6
// speedup vs baseline: 2.9356x; 2.9356x over previous
#include <cuda_runtime.h>

#define BB 4
#define LL 4096
#define DD 1024
#define CC 64   // chunks per batch for the two-level scan

// Scratch (device globals; no allocation allowed in kernel_launch)
__device__ float  g_H[(size_t)BB * LL * DD];     // chunk-LOCAL scan values
__device__ float  g_ps[BB * LL];                 // compacted clipped boundary probs
__device__ float  g_hend[BB * CC * DD];          // chunk-end local h
__device__ float  g_carry[BB * CC * DD];         // h entering each chunk (global)
__device__ float  g_A[BB * CC];                  // per-chunk total decay (scalar)
__device__ float2 g_tok[BB * LL];                // per token: {packed(c,k), dec[c]}
__device__ int    g_nb[BB];                      // boundary count per batch
__device__ int    g_T[BB];                       // chunk size = ceil(nb/CC)
__device__ int    g_mtype;                       // 0 = uint8, 1 = int32, 2 = float32

// ---------------------------------------------------------------------------
// Kernel 0: detect storage type of boundary_mask (token 0 is always True).
//   float32 -> bytes [00 00 80 3F]; int32 -> zeros at pos%4!=0; uint8 -> dense.
// ---------------------------------------------------------------------------
__global__ void detect_kernel(const unsigned char* __restrict__ mask) {
    __shared__ int misaligned_nonzero[1];
    if (threadIdx.x == 0) misaligned_nonzero[0] = 0;
    __syncthreads();
    int found = 0;
    for (int i = threadIdx.x; i < LL * BB; i += blockDim.x) {
        if ((i & 3) != 0 && mask[i] != 0) found = 1;
    }
    if (found) atomicOr(misaligned_nonzero, 1);
    __syncthreads();
    if (threadIdx.x == 0) {
        if (mask[2] == 0x80 && mask[3] == 0x3F) g_mtype = 2;
        else if (misaligned_nonzero[0])         g_mtype = 0;
        else                                    g_mtype = 1;
    }
}

__device__ __forceinline__ int read_mask(const unsigned char* mask, int idx, int mtype) {
    if (mtype == 1) return ((const int*)mask)[idx] != 0;
    if (mtype == 2) return ((const float*)mask)[idx] != 0.0f;
    return mask[idx] != 0;
}

// ---------------------------------------------------------------------------
// Kernel A (prep): per batch (1 block of 1024 threads):
//  phase1: prefix-sum mask -> c(l); compact clipped p into s_ps/g_ps; nb.
//  phase2: per-chunk cumulative decay s_dec[t] and total decay A[b][k].
//  phase3: pack per-token record {c | k<<16, dec[c]} for the scatter kernel.
// ---------------------------------------------------------------------------
__global__ void prep_kernel(const float* __restrict__ prob,
                            const unsigned char* __restrict__ mask) {
    __shared__ float s_ps[LL];
    __shared__ float s_dec[LL];
    __shared__ int   wsum[32];
    __shared__ int   s_nb;

    int b    = blockIdx.x;
    int tid  = threadIdx.x;          // 0..1023
    int base = tid * 4;
    int mtype = g_mtype;

    // ---- phase 1: mask prefix sum + compaction ----
    int m[4];
#pragma unroll
    for (int i = 0; i < 4; i++) m[i] = read_mask(mask, b * LL + base + i, mtype);
    int tsum = m[0] + m[1] + m[2] + m[3];

    int lane = tid & 31, wid = tid >> 5;
    int v = tsum;
#pragma unroll
    for (int o = 1; o < 32; o <<= 1) {
        int n = __shfl_up_sync(0xffffffffu, v, o);
        if (lane >= o) v += n;
    }
    if (lane == 31) wsum[wid] = v;
    __syncthreads();
    if (wid == 0) {
        int wv = wsum[lane];
#pragma unroll
        for (int o = 1; o < 32; o <<= 1) {
            int n = __shfl_up_sync(0xffffffffu, wv, o);
            if (lane >= o) wv += n;
        }
        wsum[lane] = wv;
    }
    __syncthreads();
    int warpExcl   = (wid == 0) ? 0 : wsum[wid - 1];
    int threadExcl = warpExcl + (v - tsum);

    int cloc[4];
    int run = threadExcl;
#pragma unroll
    for (int i = 0; i < 4; i++) {
        run += m[i];
        cloc[i] = run - 1;
        if (m[i]) {
            float p = prob[((size_t)b * LL + base + i) * 2 + 1];
            p = fminf(fmaxf(p, 1e-4f), 1.0f - 1e-4f);
            s_ps[run - 1] = p;
            g_ps[(size_t)b * LL + (run - 1)] = p;
        }
    }
    if (tid == 1023) { s_nb = run; g_nb[b] = run; }
    __syncthreads();

    // ---- phase 2: per-chunk cumulative decay ----
    int nb = s_nb;
    int T  = (nb + CC - 1) / CC;
    if (tid == 0) g_T[b] = T;
    if (tid < CC) {
        int t0 = tid * T;
        int t1 = min(t0 + T, nb);
        float prod = 1.0f;
        for (int t = t0; t < t1; t++) {
            prod *= (1.0f - s_ps[t]);
            s_dec[t] = prod;
        }
        g_A[b * CC + tid] = prod;   // 1.0 for empty chunks
    }
    __syncthreads();

    // ---- phase 3: pack per-token record ----
#pragma unroll
    for (int i = 0; i < 4; i++) {
        int c = cloc[i];
        int k = c / T;
        g_tok[(size_t)b * LL + base + i] =
            make_float2(__int_as_float(c | (k << 16)), s_dec[c]);
    }
}

// ---------------------------------------------------------------------------
// Kernel B (pass 1): chunk-local scan. Grid (CC, B) x 1024 threads (one per d).
// h starts at 0 at each chunk; writes local H and chunk-end hend.
// x load is software-pipelined one iteration ahead so the dependent-FMA chain
// never waits on the next DRAM load.
// ---------------------------------------------------------------------------
__global__ void scan_chunk_kernel(const float* __restrict__ hidden) {
    int b = blockIdx.y;
    int k = blockIdx.x;
    int d = threadIdx.x;
    int nb = g_nb[b];
    int T  = g_T[b];
    int t0 = k * T;
    int t1 = min(t0 + T, nb);

    const float* x  = hidden + (size_t)b * LL * DD + d;
    float*       Hl = g_H    + (size_t)b * LL * DD + d;
    const float* ps = g_ps   + (size_t)b * LL;

    float h = 0.0f;
    if (t0 < t1) {
        float xn = x[(size_t)t0 * DD];
        float pn = ps[t0];
        for (int t = t0; t < t1 - 1; t++) {
            float xc = xn, pc = pn;
            xn = x[(size_t)(t + 1) * DD];     // prefetch next (independent of h)
            pn = ps[t + 1];
            h = fmaf(1.0f - pc, h, pc * xc);
            Hl[(size_t)t * DD] = h;
        }
        h = fmaf(1.0f - pn, h, pn * xn);
        Hl[(size_t)(t1 - 1) * DD] = h;
    }
    g_hend[(b * CC + k) * DD + d] = h;
}

// ---------------------------------------------------------------------------
// Kernel C (pass 2): carry scan across chunks per (b,d).
// carry[k] = value of h entering chunk k. A is a per-(b,k) scalar.
// ---------------------------------------------------------------------------
__global__ void carry_kernel() {
    int b = blockIdx.x;
    int d = threadIdx.x;
    const float* A  = g_A    + b * CC;
    const float* he = g_hend + (size_t)b * CC * DD + d;
    float*       cr = g_carry + (size_t)b * CC * DD + d;

    float carry = 0.0f;
#pragma unroll
    for (int k = 0; k < CC; k++) {
        cr[(size_t)k * DD] = carry;
        carry = fmaf(A[k], carry, he[(size_t)k * DD]);
    }
}

// ---------------------------------------------------------------------------
// Kernel D (scatter + fix-up): out[b,l,:] = Hl[b,c,:] + dec[b,c]*carry[b,k,:]
// ---------------------------------------------------------------------------
__global__ void scatter_kernel(float* __restrict__ out) {
    int idx = blockIdx.x * blockDim.x + threadIdx.x;  // over B*L*256
    int row = idx >> 8;     // b*L + l
    int d4  = idx & 255;
    int b   = row >> 12;    // L = 4096

    float2 tok = g_tok[row];
    int ck = __float_as_int(tok.x);
    int c  = ck & 0xFFFF;
    int k  = ck >> 16;
    float dec = tok.y;

    const float4* Hv = (const float4*)g_H;
    const float4* Cv = (const float4*)g_carry;
    float4 h  = Hv[((size_t)b * LL + c) * 256 + d4];
    float4 cy = Cv[((size_t)(b * CC + k)) * 256 + d4];
    float4 r;
    r.x = fmaf(dec, cy.x, h.x);
    r.y = fmaf(dec, cy.y, h.y);
    r.z = fmaf(dec, cy.z, h.z);
    r.w = fmaf(dec, cy.w, h.w);
    ((float4*)out)[idx] = r;
}

extern "C" void kernel_launch(void* const* d_in, const int* in_sizes, int n_in,
                              void* d_out, int out_size) {
    const float*         hidden = (const float*)d_in[0];
    const float*         prob   = (const float*)d_in[1];
    const unsigned char* mask   = (const unsigned char*)d_in[2];
    float*               out    = (float*)d_out;

    detect_kernel<<<1, 512>>>(mask);
    prep_kernel<<<BB, 1024>>>(prob, mask);
    scan_chunk_kernel<<<dim3(CC, BB), 1024>>>(hidden);
    carry_kernel<<<BB, 1024>>>();
    scatter_kernel<<<BB * LL, 256>>>(out);
}

// round 7
// speedup vs baseline: 3.9331x; 1.3398x over previous
#include <cuda_runtime.h>

#define BB 4
#define LL 4096
#define DD 1024
#define CC 64   // chunks per batch for the two-level scan

// Scratch (device globals; no allocation allowed in kernel_launch)
__device__ float  g_H[(size_t)BB * LL * DD];     // chunk-LOCAL scan values
__device__ float  g_ps[BB * LL];                 // compacted clipped boundary probs
__device__ float  g_hend[BB * CC * DD];          // chunk-end local h
__device__ float  g_carry[BB * CC * DD];         // h entering each chunk (global)
__device__ float  g_A[BB * CC];                  // per-chunk total decay (scalar)
__device__ float2 g_tok[BB * LL];                // per token: {packed(c,k), dec[c]}
__device__ int    g_nb[BB];                      // boundary count per batch
__device__ int    g_T[BB];                       // chunk size = ceil(nb/CC)
__device__ int    g_mtype;                       // 0 = uint8, 1 = int32, 2 = float32

// ---------------------------------------------------------------------------
// Kernel 0: detect storage type of boundary_mask (token 0 is always True).
//   float32 -> bytes [00 00 80 3F]; int32 -> zeros at pos%4!=0; uint8 -> dense.
// ---------------------------------------------------------------------------
__global__ void detect_kernel(const unsigned char* __restrict__ mask) {
    __shared__ int misaligned_nonzero[1];
    if (threadIdx.x == 0) misaligned_nonzero[0] = 0;
    __syncthreads();
    int found = 0;
    for (int i = threadIdx.x; i < LL * BB; i += blockDim.x) {
        if ((i & 3) != 0 && mask[i] != 0) found = 1;
    }
    if (found) atomicOr(misaligned_nonzero, 1);
    __syncthreads();
    if (threadIdx.x == 0) {
        if (mask[2] == 0x80 && mask[3] == 0x3F) g_mtype = 2;
        else if (misaligned_nonzero[0])         g_mtype = 0;
        else                                    g_mtype = 1;
    }
}

__device__ __forceinline__ int read_mask(const unsigned char* mask, int idx, int mtype) {
    if (mtype == 1) return ((const int*)mask)[idx] != 0;
    if (mtype == 2) return ((const float*)mask)[idx] != 0.0f;
    return mask[idx] != 0;
}

// ---------------------------------------------------------------------------
// Kernel A (prep): per batch (1 block of 1024 threads):
//  phase1: prefix-sum mask -> c(l); compact clipped p into s_ps/g_ps; nb.
//  phase2: per-chunk cumulative decay s_dec[t] and total decay A[b][k].
//  phase3: pack per-token record {c | k<<16, dec[c]} for the scatter kernel.
// ---------------------------------------------------------------------------
__global__ void prep_kernel(const float* __restrict__ prob,
                            const unsigned char* __restrict__ mask) {
    __shared__ float s_ps[LL];
    __shared__ float s_dec[LL];
    __shared__ int   wsum[32];
    __shared__ int   s_nb;

    int b    = blockIdx.x;
    int tid  = threadIdx.x;          // 0..1023
    int base = tid * 4;
    int mtype = g_mtype;

    // ---- phase 1: mask prefix sum + compaction ----
    int m[4];
#pragma unroll
    for (int i = 0; i < 4; i++) m[i] = read_mask(mask, b * LL + base + i, mtype);
    int tsum = m[0] + m[1] + m[2] + m[3];

    int lane = tid & 31, wid = tid >> 5;
    int v = tsum;
#pragma unroll
    for (int o = 1; o < 32; o <<= 1) {
        int n = __shfl_up_sync(0xffffffffu, v, o);
        if (lane >= o) v += n;
    }
    if (lane == 31) wsum[wid] = v;
    __syncthreads();
    if (wid == 0) {
        int wv = wsum[lane];
#pragma unroll
        for (int o = 1; o < 32; o <<= 1) {
            int n = __shfl_up_sync(0xffffffffu, wv, o);
            if (lane >= o) wv += n;
        }
        wsum[lane] = wv;
    }
    __syncthreads();
    int warpExcl   = (wid == 0) ? 0 : wsum[wid - 1];
    int threadExcl = warpExcl + (v - tsum);

    int cloc[4];
    int run = threadExcl;
#pragma unroll
    for (int i = 0; i < 4; i++) {
        run += m[i];
        cloc[i] = run - 1;
        if (m[i]) {
            float p = prob[((size_t)b * LL + base + i) * 2 + 1];
            p = fminf(fmaxf(p, 1e-4f), 1.0f - 1e-4f);
            s_ps[run - 1] = p;
            g_ps[(size_t)b * LL + (run - 1)] = p;
        }
    }
    if (tid == 1023) { s_nb = run; g_nb[b] = run; }
    __syncthreads();

    // ---- phase 2: per-chunk cumulative decay ----
    int nb = s_nb;
    int T  = (nb + CC - 1) / CC;
    if (tid == 0) g_T[b] = T;
    if (tid < CC) {
        int t0 = tid * T;
        int t1 = min(t0 + T, nb);
        float prod = 1.0f;
        for (int t = t0; t < t1; t++) {
            prod *= (1.0f - s_ps[t]);
            s_dec[t] = prod;
        }
        g_A[b * CC + tid] = prod;   // 1.0 for empty chunks
    }
    __syncthreads();

    // ---- phase 3: pack per-token record ----
#pragma unroll
    for (int i = 0; i < 4; i++) {
        int c = cloc[i];
        int k = c / T;
        g_tok[(size_t)b * LL + base + i] =
            make_float2(__int_as_float(c | (k << 16)), s_dec[c]);
    }
}

// ---------------------------------------------------------------------------
// Kernel B (pass 1): chunk-local scan. Grid (CC, B) x 1024 threads (one per d).
// h starts at 0 at each chunk; writes local H and chunk-end hend.
// x load is software-pipelined one iteration ahead so the dependent-FMA chain
// never waits on the next DRAM load.
// ---------------------------------------------------------------------------
__global__ void scan_chunk_kernel(const float* __restrict__ hidden) {
    int b = blockIdx.y;
    int k = blockIdx.x;
    int d = threadIdx.x;
    int nb = g_nb[b];
    int T  = g_T[b];
    int t0 = k * T;
    int t1 = min(t0 + T, nb);

    const float* x  = hidden + (size_t)b * LL * DD + d;
    float*       Hl = g_H    + (size_t)b * LL * DD + d;
    const float* ps = g_ps   + (size_t)b * LL;

    float h = 0.0f;
    if (t0 < t1) {
        float xn = x[(size_t)t0 * DD];
        float pn = ps[t0];
        for (int t = t0; t < t1 - 1; t++) {
            float xc = xn, pc = pn;
            xn = x[(size_t)(t + 1) * DD];     // prefetch next (independent of h)
            pn = ps[t + 1];
            h = fmaf(1.0f - pc, h, pc * xc);
            Hl[(size_t)t * DD] = h;
        }
        h = fmaf(1.0f - pn, h, pn * xn);
        Hl[(size_t)(t1 - 1) * DD] = h;
    }
    g_hend[(b * CC + k) * DD + d] = h;
}

// ---------------------------------------------------------------------------
// Kernel C (pass 2): carry scan across chunks per (b,d).
// v2: 32 blocks x 128 threads. All 64 hend values are preloaded into a fully
// unrolled register array (64 independent LDGs in flight -> one latency wait),
// then the 64-step FMA chain runs register-resident. A is staged in smem.
// ---------------------------------------------------------------------------
__global__ void carry_kernel() {
    int b = blockIdx.y;
    int d = blockIdx.x * 128 + threadIdx.x;

    __shared__ float sA[CC];
    if (threadIdx.x < CC) sA[threadIdx.x] = g_A[b * CC + threadIdx.x];
    __syncthreads();

    const float* he = g_hend  + (size_t)b * CC * DD + d;
    float*       cr = g_carry + (size_t)b * CC * DD + d;

    float v[CC];
#pragma unroll
    for (int k = 0; k < CC; k++) v[k] = he[(size_t)k * DD];   // batched MLP loads

    float carry = 0.0f;
#pragma unroll
    for (int k = 0; k < CC; k++) {
        cr[(size_t)k * DD] = carry;
        carry = fmaf(sA[k], carry, v[k]);
    }
}

// ---------------------------------------------------------------------------
// Kernel D (scatter + fix-up): out[b,l,:] = Hl[b,c,:] + dec[b,c]*carry[b,k,:]
// ---------------------------------------------------------------------------
__global__ void scatter_kernel(float* __restrict__ out) {
    int idx = blockIdx.x * blockDim.x + threadIdx.x;  // over B*L*256
    int row = idx >> 8;     // b*L + l
    int d4  = idx & 255;
    int b   = row >> 12;    // L = 4096

    float2 tok = g_tok[row];
    int ck = __float_as_int(tok.x);
    int c  = ck & 0xFFFF;
    int k  = ck >> 16;
    float dec = tok.y;

    const float4* Hv = (const float4*)g_H;
    const float4* Cv = (const float4*)g_carry;
    float4 h  = Hv[((size_t)b * LL + c) * 256 + d4];
    float4 cy = Cv[((size_t)(b * CC + k)) * 256 + d4];
    float4 r;
    r.x = fmaf(dec, cy.x, h.x);
    r.y = fmaf(dec, cy.y, h.y);
    r.z = fmaf(dec, cy.z, h.z);
    r.w = fmaf(dec, cy.w, h.w);
    ((float4*)out)[idx] = r;
}

extern "C" void kernel_launch(void* const* d_in, const int* in_sizes, int n_in,
                              void* d_out, int out_size) {
    const float*         hidden = (const float*)d_in[0];
    const float*         prob   = (const float*)d_in[1];
    const unsigned char* mask   = (const unsigned char*)d_in[2];
    float*               out    = (float*)d_out;

    detect_kernel<<<1, 512>>>(mask);
    prep_kernel<<<BB, 1024>>>(prob, mask);
    scan_chunk_kernel<<<dim3(CC, BB), 1024>>>(hidden);
    carry_kernel<<<dim3(DD / 128, BB), 128>>>();
    scatter_kernel<<<BB * LL, 256>>>(out);
}